// round 13
// baseline (speedup 1.0000x reference)
#include <cuda_runtime.h>
#include <cuda_bf16.h>
#include <cstdint>
#include <cfloat>

// Problem constants (fixed by the reference)
#define NW        4
#define CCH       32
#define MPW       8
#define IMG_H     1024
#define IMG_W     1024
#define HW        (IMG_H * IMG_W)
#define WIN_H     512
#define WIN_W     512
#define SLOT_DIM  64
#define SIM_THRESH 0.1f
#define P_MAX     304

#define NTHR      256        // threads per block (R9/R12 proven)
#define CHUNK     2048       // pixels per block (R9/R12 proven)
#define PPT       8          // pixels per thread
#define NDUTY     128        // edge-duty blocks (16 edges x 8 slices of 64px)
#define GRID      (HW / CHUNK)   // 512

// Scratch (device globals; zero-initialized at load, self-reset each launch)
__device__ unsigned d_edge_s[16][8];   // [window*4+edge][eighth] bitmasks
__device__ int      d_map[CCH];
__device__ unsigned d_arrive;          // duty arrival counter
__device__ int      d_ready;           // map-ready flag
__device__ unsigned d_done;            // blocks past the spin (for self-reset)

__device__ __forceinline__ uint32_t smem_u32(const void* p) {
    return (uint32_t)__cvta_generic_to_shared(p);
}

// ---------------------------------------------------------------------------
// Single kernel (R12 structure). Blocks 0..127 compute one edge slice first;
// block 127 gathers all slices, computes the merge map, publishes it.
// All blocks: channel-ROTATED argmax reads (row-locality) -> flag spin ->
// remap -> double-buffered bulk-store writes. Last block past the spin
// resets the sync words for the next graph replay.
// ---------------------------------------------------------------------------
__global__ void __launch_bounds__(NTHR) main_kernel(
    const float* __restrict__ masks,
    float* __restrict__ out,
    const float* __restrict__ sf,
    const int* __restrict__ pad_left,
    const int* __restrict__ pad_top)
{
    __shared__ __align__(16) float sbuf[2][CHUNK];     // 16KB write staging
    __shared__ int smap[CCH];

    const int bid = blockIdx.x;
    const int t   = threadIdx.x;

    // ---------------- edge duty (blocks 0..127) ----------------
    if (bid < NDUTY) {
        __shared__ float sb[64][4];
        __shared__ int   si[64][4];

        const int ei  = bid >> 3;         // window*4+edge
        const int sub = bid & 7;          // eighth (64 px)
        const int w   = ei >> 2;
        const int e   = ei & 3;           // 0=L 1=R 2=T 3=B

        int pl = pad_left[w], pt = pad_top[w];
        int ys = max(pt, 0), ye = min(pt + WIN_H, IMG_H);
        int xs = max(pl, 0), xe = min(pl + WIN_W, IMG_W);

        const int px  = t & 63;
        const int grp = t >> 6;           // channel group 0..3 (8 ch each)
        const int k   = sub * 64 + px;

        float best = -INFINITY;
        int   id   = grp * 8;
        if (ys < ye && xs < xe) {
            int len = (e < 2) ? (ye - ys) : (xe - xs);
            if (k < len) {
                int y, x;
                if      (e == 0) { y = ys + k; x = xs;     }
                else if (e == 1) { y = ys + k; x = xe - 1; }
                else if (e == 2) { y = ys;     x = xs + k; }
                else             { y = ye - 1; x = xs + k; }
                const float* p = masks + (size_t)(grp * 8) * HW + (size_t)y * IMG_W + x;
                #pragma unroll
                for (int c8 = 0; c8 < 8; c8++) {
                    float v = __ldg(p + (size_t)c8 * HW);
                    if (v > best) { best = v; id = grp * 8 + c8; }
                }
            }
        }
        sb[px][grp] = best;
        si[px][grp] = id;
        __syncthreads();

        unsigned bit = 0u;
        if (t < 64) {
            bool valid = false;
            if (ys < ye && xs < xe) {
                int len = (e < 2) ? (ye - ys) : (xe - xs);
                valid = (k < len);
            }
            if (valid) {
                float b = sb[t][0];
                int   i = si[t][0];
                #pragma unroll
                for (int g = 1; g < 4; g++) {
                    float bg = sb[t][g];
                    if (bg > b) { b = bg; i = si[t][g]; }
                }
                if ((i >> 3) == w) bit = 1u << i;
            }
        }
        unsigned wm = __reduce_or_sync(0xffffffffu, (t < 64) ? bit : 0u);
        __shared__ unsigned sw[2];
        if (t == 0)  sw[0] = wm;
        if (t == 32) sw[1] = wm;
        __syncthreads();
        if (t == 0) {
            d_edge_s[ei][sub] = sw[0] | sw[1];
            __threadfence();
            atomicAdd(&d_arrive, 1u);
        }
        __syncthreads();

        // ---------------- map computation (block 127 only) ----------------
        if (bid == NDUTY - 1) {
            if (t == 0) {
                while (*(volatile unsigned*)&d_arrive < (unsigned)NDUTY)
                    __nanosleep(64);
                __threadfence();
            }
            __syncthreads();

            __shared__ int  s_ci[P_MAX];
            __shared__ int  s_cj[P_MAX];
            __shared__ char s_hz[P_MAX];
            __shared__ char s_pass[P_MAX];
            __shared__ int  s_P;
            __shared__ unsigned s_edge[NW][4];

            if (t < 16) {
                unsigned a = 0;
                #pragma unroll
                for (int i = 0; i < 8; i++) a |= d_edge_s[t][i];
                s_edge[t >> 2][t & 3] = a;
            }
            if (t == 0) {
                int pl2[NW], pt2[NW];
                for (int i = 0; i < NW; i++) { pl2[i] = pad_left[i]; pt2[i] = pad_top[i]; }
                int na = 0;
                int ai[12], aj[12]; char ah[12];
                for (int i = 0; i < NW; i++) {
                    for (int j = i + 1; j < NW; j++) {
                        if (pt2[i] == pt2[j] && abs(pl2[i] - pl2[j]) == WIN_W) {
                            if (pl2[i] < pl2[j]) { ai[na] = i; aj[na] = j; }
                            else                  { ai[na] = j; aj[na] = i; }
                            ah[na] = 1; na++;
                        }
                        if (pl2[i] == pl2[j] && abs(pt2[i] - pt2[j]) == WIN_H) {
                            if (pt2[i] < pt2[j]) { ai[na] = i; aj[na] = j; }
                            else                  { ai[na] = j; aj[na] = i; }
                            ah[na] = 0; na++;
                        }
                    }
                }
                int P = 0;
                for (int a = 0; a < na; a++) {
                    int si2 = ai[a] * MPW, sj2 = aj[a] * MPW;
                    for (int ci = si2 + 1; ci < si2 + MPW; ci++)
                        for (int cj = sj2 + 1; cj < sj2 + MPW; cj++) {
                            s_ci[P] = ci; s_cj[P] = cj; s_hz[P] = ah[a]; P++;
                        }
                }
                s_P = P;
            }
            __syncthreads();

            int P = s_P;
            for (int p = t; p < P; p += NTHR) {
                int ci = s_ci[p], cj = s_cj[p];
                int wi = ci / MPW, wj = cj / MPW;
                int ri = ci % MPW - 1, rj = cj % MPW - 1;
                const float* fi = sf + ((long long)wi * (MPW - 1) + ri) * SLOT_DIM;
                const float* fj = sf + ((long long)wj * (MPW - 1) + rj) * SLOT_DIM;
                float dot = 0.f, ni = 0.f, nj = 0.f;
                #pragma unroll
                for (int q = 0; q < SLOT_DIM; q++) {
                    float a = fi[q], b = fj[q];
                    dot += a * b; ni += a * a; nj += b * b;
                }
                float sim = dot / ((sqrtf(ni) + 1e-8f) * (sqrtf(nj) + 1e-8f));
                bool ok;
                if (s_hz[p]) {
                    ok = ((s_edge[wi][1] >> ci) & 1u) && ((s_edge[wj][0] >> cj) & 1u);
                } else {
                    ok = ((s_edge[wi][3] >> ci) & 1u) && ((s_edge[wj][2] >> cj) & 1u);
                }
                s_pass[p] = (ok && sim > SIM_THRESH) ? 1 : 0;
            }
            __syncthreads();

            if (t == 0) {
                int mp[CCH];
                bool merged[CCH];
                for (int c = 0; c < CCH; c++) { mp[c] = c; merged[c] = false; }
                for (int p = 0; p < P; p++) {
                    int ci = s_ci[p], cj = s_cj[p];
                    if (s_pass[p] && !merged[ci] && !merged[cj]) {
                        int keep = min(ci, cj), rem = max(ci, cj);
                        for (int c = 0; c < CCH; c++)
                            if (mp[c] == rem) mp[c] = keep;
                        merged[rem] = true;
                    }
                }
                for (int c = 0; c < CCH; c++) d_map[c] = mp[c];
                __threadfence();
                *(volatile int*)&d_ready = 1;
            }
            __syncthreads();
        }
    }

    // ---------------- main argmax reads: per-block channel rotation ---------
    // Block bid reads channels in order (rot, rot+1, ..., rot+31) mod 32, so
    // at any instant only ~16 blocks stream each plane -> long DRAM row runs.
    // First-max-wins preserved via ==-tiebreak on the true channel index.
    const size_t base = (size_t)bid * CHUNK;
    const int stride4 = HW / 4;
    const int idx = bid * (CHUNK / 4) + t * (PPT / 4);
    const float4* m4 = (const float4*)masks;
    const int rot = bid & 31;

    float best[PPT];
    int   ida[PPT];
    {
        float4 a = __ldcs(&m4[(size_t)rot * stride4 + idx]);
        float4 b = __ldcs(&m4[(size_t)rot * stride4 + idx + 1]);
        best[0] = a.x; best[1] = a.y; best[2] = a.z; best[3] = a.w;
        best[4] = b.x; best[5] = b.y; best[6] = b.z; best[7] = b.w;
        #pragma unroll
        for (int i = 0; i < PPT; i++) ida[i] = rot;
    }
    // prefetch second channel
    {
        int cn = (rot + 1) & 31;
        float4 pa = __ldcs(&m4[(size_t)cn * stride4 + idx]);
        float4 pb = __ldcs(&m4[(size_t)cn * stride4 + idx + 1]);
        #pragma unroll
        for (int cc = 1; cc < CCH; cc++) {
            const int c = (rot + cc) & 31;          // true channel index
            float4 a = pa, b = pb;
            if (cc + 1 < CCH) {
                int c2 = (rot + cc + 1) & 31;
                pa = __ldcs(&m4[(size_t)c2 * stride4 + idx]);
                pb = __ldcs(&m4[(size_t)c2 * stride4 + idx + 1]);
            }
            float v[PPT] = {a.x, a.y, a.z, a.w, b.x, b.y, b.z, b.w};
            #pragma unroll
            for (int i = 0; i < PPT; i++) {
                if (v[i] > best[i] || (v[i] == best[i] && c < ida[i])) {
                    best[i] = v[i]; ida[i] = c;
                }
            }
        }
    }

    // ---------------- wait for map (already published; near-zero wait) ------
    if (t == 0) {
        while (!*(volatile int*)&d_ready)
            __nanosleep(64);
        __threadfence();
    }
    __syncthreads();
    if (t < CCH) smap[t] = d_map[t];
    __syncthreads();

    // self-reset for next graph replay: last block past the spin clears flags
    if (t == 0) {
        unsigned old = atomicAdd(&d_done, 1u);
        if (old == (unsigned)(GRID - 1)) {
            d_arrive = 0u;
            d_ready  = 0;
            d_done   = 0u;
        }
    }

    #pragma unroll
    for (int i = 0; i < PPT; i++) ida[i] = smap[ida[i]];

    // ---------------- staged one-hot writes (double-buffered bulk stores) ---
    for (int c = 0; c < CCH; c++) {
        int buf = c & 1;
        if (c >= 2) {
            if (t == 0)
                asm volatile("cp.async.bulk.wait_group.read 1;" ::: "memory");
            __syncthreads();
        }
        float4* sb4 = (float4*)(&sbuf[buf][0] + t * PPT);
        float4 o1, o2;
        o1.x = (ida[0] == c) ? 1.0f : 0.0f;
        o1.y = (ida[1] == c) ? 1.0f : 0.0f;
        o1.z = (ida[2] == c) ? 1.0f : 0.0f;
        o1.w = (ida[3] == c) ? 1.0f : 0.0f;
        o2.x = (ida[4] == c) ? 1.0f : 0.0f;
        o2.y = (ida[5] == c) ? 1.0f : 0.0f;
        o2.z = (ida[6] == c) ? 1.0f : 0.0f;
        o2.w = (ida[7] == c) ? 1.0f : 0.0f;
        sb4[0] = o1; sb4[1] = o2;
        __syncthreads();
        if (t == 0) {
            float* gdst = out + (size_t)c * HW + base;
            uint32_t saddr = smem_u32(&sbuf[buf][0]);
            asm volatile("fence.proxy.async.shared::cta;" ::: "memory");
            asm volatile(
                "cp.async.bulk.global.shared::cta.bulk_group [%0], [%1], %2;"
                :: "l"(gdst), "r"(saddr), "n"(CHUNK * 4) : "memory");
            asm volatile("cp.async.bulk.commit_group;" ::: "memory");
        }
    }
    if (t == 0)
        asm volatile("cp.async.bulk.wait_group.read 0;" ::: "memory");
    __syncthreads();
}

// ---------------------------------------------------------------------------
extern "C" void kernel_launch(void* const* d_in, const int* in_sizes, int n_in,
                              void* d_out, int out_size)
{
    const float* masks = (const float*)d_in[0];
    const float* sf    = (const float*)d_in[1];
    const int*   pl    = (const int*)d_in[2];
    const int*   pt    = (const int*)d_in[3];
    float*       out   = (float*)d_out;

    main_kernel<<<GRID, NTHR>>>(masks, out, sf, pl, pt);
}

// round 15
// speedup vs baseline: 1.0114x; 1.0114x over previous
#include <cuda_runtime.h>
#include <cuda_bf16.h>
#include <cstdint>
#include <cfloat>

// Problem constants (fixed by the reference)
#define NW        4
#define CCH       32
#define MPW       8
#define IMG_H     1024
#define IMG_W     1024
#define HW        (IMG_H * IMG_W)
#define WIN_H     512
#define WIN_W     512
#define SLOT_DIM  64
#define SIM_THRESH 0.1f
#define P_MAX     304

#define NTHR      256        // threads per block
#define CHUNK     2048       // pixels per block
#define PPT       8          // pixels per thread
#define NDUTY     128        // edge-duty blocks (16 edges x 8 slices of 64px)
#define GRID      (HW / CHUNK)   // 512

// Scratch (device globals; zero-initialized at load, self-reset each launch)
__device__ unsigned d_edge_s[16][8];   // [window*4+edge][eighth] bitmasks
__device__ int      d_map[CCH];
__device__ unsigned d_arrive;          // duty arrival counter
__device__ int      d_ready;           // map-ready flag
__device__ unsigned d_done;            // blocks past the spin (for self-reset)

__device__ __forceinline__ uint32_t smem_u32(const void* p) {
    return (uint32_t)__cvta_generic_to_shared(p);
}

// evict_last (policy form) vector load: keep masks L2-resident across replays
__device__ __forceinline__ float4 ldg_el(const float4* p, uint64_t pol) {
    float4 r;
    asm volatile("ld.global.nc.L2::cache_hint.v4.f32 {%0,%1,%2,%3}, [%4], %5;"
                 : "=f"(r.x), "=f"(r.y), "=f"(r.z), "=f"(r.w)
                 : "l"(p), "l"(pol));
    return r;
}

// ---------------------------------------------------------------------------
// Single kernel (R13 structure). Blocks 0..127 compute one edge slice first;
// block 127 gathers all slices, computes the merge map, publishes it.
// All blocks: channel-rotated evict_last argmax reads -> flag spin -> remap ->
// double-buffered bulk stores with evict_first L2 policy. Last block past the
// spin resets the sync words for the next graph replay.
// ---------------------------------------------------------------------------
__global__ void __launch_bounds__(NTHR) main_kernel(
    const float* __restrict__ masks,
    float* __restrict__ out,
    const float* __restrict__ sf,
    const int* __restrict__ pad_left,
    const int* __restrict__ pad_top)
{
    __shared__ __align__(16) float sbuf[2][CHUNK];     // 16KB write staging
    __shared__ int smap[CCH];

    const int bid = blockIdx.x;
    const int t   = threadIdx.x;

    // ---------------- edge duty (blocks 0..127) ----------------
    if (bid < NDUTY) {
        __shared__ float sb[64][4];
        __shared__ int   si[64][4];

        const int ei  = bid >> 3;         // window*4+edge
        const int sub = bid & 7;          // eighth (64 px)
        const int w   = ei >> 2;
        const int e   = ei & 3;           // 0=L 1=R 2=T 3=B

        int pl = pad_left[w], pt = pad_top[w];
        int ys = max(pt, 0), ye = min(pt + WIN_H, IMG_H);
        int xs = max(pl, 0), xe = min(pl + WIN_W, IMG_W);

        const int px  = t & 63;
        const int grp = t >> 6;           // channel group 0..3 (8 ch each)
        const int k   = sub * 64 + px;

        float best = -INFINITY;
        int   id   = grp * 8;
        if (ys < ye && xs < xe) {
            int len = (e < 2) ? (ye - ys) : (xe - xs);
            if (k < len) {
                int y, x;
                if      (e == 0) { y = ys + k; x = xs;     }
                else if (e == 1) { y = ys + k; x = xe - 1; }
                else if (e == 2) { y = ys;     x = xs + k; }
                else             { y = ye - 1; x = xs + k; }
                const float* p = masks + (size_t)(grp * 8) * HW + (size_t)y * IMG_W + x;
                #pragma unroll
                for (int c8 = 0; c8 < 8; c8++) {
                    float v = __ldg(p + (size_t)c8 * HW);
                    if (v > best) { best = v; id = grp * 8 + c8; }
                }
            }
        }
        sb[px][grp] = best;
        si[px][grp] = id;
        __syncthreads();

        unsigned bit = 0u;
        if (t < 64) {
            bool valid = false;
            if (ys < ye && xs < xe) {
                int len = (e < 2) ? (ye - ys) : (xe - xs);
                valid = (k < len);
            }
            if (valid) {
                float b = sb[t][0];
                int   i = si[t][0];
                #pragma unroll
                for (int g = 1; g < 4; g++) {
                    float bg = sb[t][g];
                    if (bg > b) { b = bg; i = si[t][g]; }
                }
                if ((i >> 3) == w) bit = 1u << i;
            }
        }
        unsigned wm = __reduce_or_sync(0xffffffffu, (t < 64) ? bit : 0u);
        __shared__ unsigned sw[2];
        if (t == 0)  sw[0] = wm;
        if (t == 32) sw[1] = wm;
        __syncthreads();
        if (t == 0) {
            d_edge_s[ei][sub] = sw[0] | sw[1];
            __threadfence();
            atomicAdd(&d_arrive, 1u);
        }
        __syncthreads();

        // ---------------- map computation (block 127 only) ----------------
        if (bid == NDUTY - 1) {
            if (t == 0) {
                while (*(volatile unsigned*)&d_arrive < (unsigned)NDUTY)
                    __nanosleep(64);
                __threadfence();
            }
            __syncthreads();

            __shared__ int  s_ci[P_MAX];
            __shared__ int  s_cj[P_MAX];
            __shared__ char s_hz[P_MAX];
            __shared__ char s_pass[P_MAX];
            __shared__ int  s_P;
            __shared__ unsigned s_edge[NW][4];

            if (t < 16) {
                unsigned a = 0;
                #pragma unroll
                for (int i = 0; i < 8; i++) a |= d_edge_s[t][i];
                s_edge[t >> 2][t & 3] = a;
            }
            if (t == 0) {
                int pl2[NW], pt2[NW];
                for (int i = 0; i < NW; i++) { pl2[i] = pad_left[i]; pt2[i] = pad_top[i]; }
                int na = 0;
                int ai[12], aj[12]; char ah[12];
                for (int i = 0; i < NW; i++) {
                    for (int j = i + 1; j < NW; j++) {
                        if (pt2[i] == pt2[j] && abs(pl2[i] - pl2[j]) == WIN_W) {
                            if (pl2[i] < pl2[j]) { ai[na] = i; aj[na] = j; }
                            else                  { ai[na] = j; aj[na] = i; }
                            ah[na] = 1; na++;
                        }
                        if (pl2[i] == pl2[j] && abs(pt2[i] - pt2[j]) == WIN_H) {
                            if (pt2[i] < pt2[j]) { ai[na] = i; aj[na] = j; }
                            else                  { ai[na] = j; aj[na] = i; }
                            ah[na] = 0; na++;
                        }
                    }
                }
                int P = 0;
                for (int a = 0; a < na; a++) {
                    int si2 = ai[a] * MPW, sj2 = aj[a] * MPW;
                    for (int ci = si2 + 1; ci < si2 + MPW; ci++)
                        for (int cj = sj2 + 1; cj < sj2 + MPW; cj++) {
                            s_ci[P] = ci; s_cj[P] = cj; s_hz[P] = ah[a]; P++;
                        }
                }
                s_P = P;
            }
            __syncthreads();

            int P = s_P;
            for (int p = t; p < P; p += NTHR) {
                int ci = s_ci[p], cj = s_cj[p];
                int wi = ci / MPW, wj = cj / MPW;
                int ri = ci % MPW - 1, rj = cj % MPW - 1;
                const float* fi = sf + ((long long)wi * (MPW - 1) + ri) * SLOT_DIM;
                const float* fj = sf + ((long long)wj * (MPW - 1) + rj) * SLOT_DIM;
                float dot = 0.f, ni = 0.f, nj = 0.f;
                #pragma unroll
                for (int q = 0; q < SLOT_DIM; q++) {
                    float a = fi[q], b = fj[q];
                    dot += a * b; ni += a * a; nj += b * b;
                }
                float sim = dot / ((sqrtf(ni) + 1e-8f) * (sqrtf(nj) + 1e-8f));
                bool ok;
                if (s_hz[p]) {
                    ok = ((s_edge[wi][1] >> ci) & 1u) && ((s_edge[wj][0] >> cj) & 1u);
                } else {
                    ok = ((s_edge[wi][3] >> ci) & 1u) && ((s_edge[wj][2] >> cj) & 1u);
                }
                s_pass[p] = (ok && sim > SIM_THRESH) ? 1 : 0;
            }
            __syncthreads();

            if (t == 0) {
                int mp[CCH];
                bool merged[CCH];
                for (int c = 0; c < CCH; c++) { mp[c] = c; merged[c] = false; }
                for (int p = 0; p < P; p++) {
                    int ci = s_ci[p], cj = s_cj[p];
                    if (s_pass[p] && !merged[ci] && !merged[cj]) {
                        int keep = min(ci, cj), rem = max(ci, cj);
                        for (int c = 0; c < CCH; c++)
                            if (mp[c] == rem) mp[c] = keep;
                        merged[rem] = true;
                    }
                }
                for (int c = 0; c < CCH; c++) d_map[c] = mp[c];
                __threadfence();
                *(volatile int*)&d_ready = 1;
            }
            __syncthreads();
        }
    }

    // ---------------- main argmax reads: rotated, evict_last policy ---------
    uint64_t rpolicy;
    asm("createpolicy.fractional.L2::evict_last.b64 %0, 1.0;" : "=l"(rpolicy));

    const size_t base = (size_t)bid * CHUNK;
    const int stride4 = HW / 4;
    const int idx = bid * (CHUNK / 4) + t * (PPT / 4);
    const float4* m4 = (const float4*)masks;
    const int rot = bid & 31;

    float best[PPT];
    int   ida[PPT];
    {
        float4 a = ldg_el(&m4[(size_t)rot * stride4 + idx], rpolicy);
        float4 b = ldg_el(&m4[(size_t)rot * stride4 + idx + 1], rpolicy);
        best[0] = a.x; best[1] = a.y; best[2] = a.z; best[3] = a.w;
        best[4] = b.x; best[5] = b.y; best[6] = b.z; best[7] = b.w;
        #pragma unroll
        for (int i = 0; i < PPT; i++) ida[i] = rot;
    }
    {
        int cn = (rot + 1) & 31;
        float4 pa = ldg_el(&m4[(size_t)cn * stride4 + idx], rpolicy);
        float4 pb = ldg_el(&m4[(size_t)cn * stride4 + idx + 1], rpolicy);
        #pragma unroll
        for (int cc = 1; cc < CCH; cc++) {
            const int c = (rot + cc) & 31;          // true channel index
            float4 a = pa, b = pb;
            if (cc + 1 < CCH) {
                int c2 = (rot + cc + 1) & 31;
                pa = ldg_el(&m4[(size_t)c2 * stride4 + idx], rpolicy);
                pb = ldg_el(&m4[(size_t)c2 * stride4 + idx + 1], rpolicy);
            }
            float v[PPT] = {a.x, a.y, a.z, a.w, b.x, b.y, b.z, b.w};
            #pragma unroll
            for (int i = 0; i < PPT; i++) {
                if (v[i] > best[i] || (v[i] == best[i] && c < ida[i])) {
                    best[i] = v[i]; ida[i] = c;
                }
            }
        }
    }

    // ---------------- wait for map (already published; near-zero wait) ------
    if (t == 0) {
        while (!*(volatile int*)&d_ready)
            __nanosleep(64);
        __threadfence();
    }
    __syncthreads();
    if (t < CCH) smap[t] = d_map[t];
    __syncthreads();

    // self-reset for next graph replay: last block past the spin clears flags
    if (t == 0) {
        unsigned old = atomicAdd(&d_done, 1u);
        if (old == (unsigned)(GRID - 1)) {
            d_arrive = 0u;
            d_ready  = 0;
            d_done   = 0u;
        }
    }

    #pragma unroll
    for (int i = 0; i < PPT; i++) ida[i] = smap[ida[i]];

    // ---------------- staged one-hot writes: evict_first bulk stores --------
    uint64_t wpolicy;
    asm("createpolicy.fractional.L2::evict_first.b64 %0, 1.0;" : "=l"(wpolicy));

    for (int c = 0; c < CCH; c++) {
        int buf = c & 1;
        if (c >= 2) {
            if (t == 0)
                asm volatile("cp.async.bulk.wait_group.read 1;" ::: "memory");
            __syncthreads();
        }
        float4* sb4 = (float4*)(&sbuf[buf][0] + t * PPT);
        float4 o1, o2;
        o1.x = (ida[0] == c) ? 1.0f : 0.0f;
        o1.y = (ida[1] == c) ? 1.0f : 0.0f;
        o1.z = (ida[2] == c) ? 1.0f : 0.0f;
        o1.w = (ida[3] == c) ? 1.0f : 0.0f;
        o2.x = (ida[4] == c) ? 1.0f : 0.0f;
        o2.y = (ida[5] == c) ? 1.0f : 0.0f;
        o2.z = (ida[6] == c) ? 1.0f : 0.0f;
        o2.w = (ida[7] == c) ? 1.0f : 0.0f;
        sb4[0] = o1; sb4[1] = o2;
        __syncthreads();
        if (t == 0) {
            float* gdst = out + (size_t)c * HW + base;
            uint32_t saddr = smem_u32(&sbuf[buf][0]);
            asm volatile("fence.proxy.async.shared::cta;" ::: "memory");
            asm volatile(
                "cp.async.bulk.global.shared::cta.bulk_group.L2::cache_hint "
                "[%0], [%1], %2, %3;"
                :: "l"(gdst), "r"(saddr), "n"(CHUNK * 4), "l"(wpolicy) : "memory");
            asm volatile("cp.async.bulk.commit_group;" ::: "memory");
        }
    }
    if (t == 0)
        asm volatile("cp.async.bulk.wait_group.read 0;" ::: "memory");
    __syncthreads();
}

// ---------------------------------------------------------------------------
extern "C" void kernel_launch(void* const* d_in, const int* in_sizes, int n_in,
                              void* d_out, int out_size)
{
    const float* masks = (const float*)d_in[0];
    const float* sf    = (const float*)d_in[1];
    const int*   pl    = (const int*)d_in[2];
    const int*   pt    = (const int*)d_in[3];
    float*       out   = (float*)d_out;

    main_kernel<<<GRID, NTHR>>>(masks, out, sf, pl, pt);
}